// round 13
// baseline (speedup 1.0000x reference)
#include <cuda_runtime.h>

#define FM_H 120
#define FM_W 120
#define FM_C 64
#define FM_HW (FM_H * FM_W)
#define N_BOX 4096

// ---------------- device scratch (no allocations allowed) ----------------
__device__ float g_fmT[FM_HW * FM_C];          // [H*W][C]  3.69 MB
__device__ float g_pooled[N_BOX * 3 * 64];     // [n][scale3|scale7|scale11] == concat[n][192]
__device__ float g_gvec[64];                   // global avg pool
__device__ __align__(16) float g_pb1eff[128];  // pb1 + gh @ p1[192:256]

// ---------------- helpers ----------------
__device__ __forceinline__ float4 relu4(float4 v) {
    v.x = fmaxf(v.x, 0.f); v.y = fmaxf(v.y, 0.f);
    v.z = fmaxf(v.z, 0.f); v.w = fmaxf(v.w, 0.f);
    return v;
}

__device__ __forceinline__ float4 half_reduce(float4 a) {
    a.x += __shfl_down_sync(0xffffffffu, a.x, 16);
    a.y += __shfl_down_sync(0xffffffffu, a.y, 16);
    a.z += __shfl_down_sync(0xffffffffu, a.z, 16);
    a.w += __shfl_down_sync(0xffffffffu, a.w, 16);
    return a;
}

// ---------------- kernel 1: transpose [C,H,W]->[H*W,C]  +  global mean ----------------
__global__ void k_prep(const float* __restrict__ fm) {
    if (blockIdx.x < FM_HW / 64) {
        __shared__ float tile[64 * 65];
        const int p0 = blockIdx.x * 64;
        const int t = threadIdx.x;
#pragma unroll
        for (int i = 0; i < 16; i++) {
            int idx = i * 256 + t;
            int c = idx >> 6, p = idx & 63;
            tile[p * 65 + c] = fm[c * FM_HW + p0 + p];
        }
        __syncthreads();
#pragma unroll
        for (int i = 0; i < 16; i++) {
            int idx = i * 256 + t;
            int p = idx >> 6, c = idx & 63;
            g_fmT[(p0 + p) * 64 + c] = tile[p * 65 + c];
        }
    } else {
        __shared__ float red[256];
        const int c = blockIdx.x - FM_HW / 64;
        float s = 0.f;
        for (int p = threadIdx.x; p < FM_HW; p += 256) s += fm[c * FM_HW + p];
        red[threadIdx.x] = s;
        __syncthreads();
        for (int st = 128; st > 0; st >>= 1) {
            if (threadIdx.x < st) red[threadIdx.x] += red[threadIdx.x + st];
            __syncthreads();
        }
        if (threadIdx.x == 0) g_gvec[c] = red[0] * (1.0f / (float)FM_HW);
    }
}

// ---------------- kernel 2: shared head on g, fold into pb1eff ----------------
__global__ void k_headg(const float* __restrict__ w1, const float* __restrict__ b1,
                        const float* __restrict__ w2, const float* __restrict__ b2,
                        const float* __restrict__ p1, const float* __restrict__ pb1) {
    __shared__ float h1[128];
    __shared__ float gh[64];
    const int t = threadIdx.x;  // 128 threads
    {
        float acc = b1[t];
#pragma unroll 8
        for (int c = 0; c < 64; c++) acc += g_gvec[c] * w1[c * 128 + t];
        h1[t] = fmaxf(acc, 0.f);
    }
    __syncthreads();
    if (t < 64) {
        float acc = b2[t];
#pragma unroll 8
        for (int k = 0; k < 128; k++) acc += h1[k] * w2[k * 64 + t];
        gh[t] = fmaxf(acc, 0.f);
    }
    __syncthreads();
    {
        float acc = pb1[t];
#pragma unroll 8
        for (int j = 0; j < 64; j++) acc += gh[j] * p1[(192 + j) * 128 + t];
        g_pb1eff[t] = acc;
    }
}

// ---------------- kernel 3: ROI pooling (unchanged) ----------------
template <int R>
__device__ __forceinline__ float4 accum_scale(const float4* __restrict__ base4,
                                              float Ax, float Sx, float Ay, float Sy,
                                              int j0, int j1, int half, int lane4) {
    const float invR = 1.0f / (float)R;
    float4 acc = make_float4(0.f, 0.f, 0.f, 0.f);
    const int steps = ((j1 - j0) + 1) >> 1;
#pragma unroll 4
    for (int i = 0; i < steps; i++) {
        int j = j0 + 2 * i + half;
        float valid = (j < j1) ? 1.f : 0.f;
        int jc = min(j, j1 - 1);
        int row = jc / R;
        int col = jc - row * R;
        float iy = Ay + Sy * ((2.0f * row + 1.0f) * invR - 1.0f);
        float ix = Ax + Sx * ((2.0f * col + 1.0f) * invR - 1.0f);
        float y0f = floorf(iy), x0f = floorf(ix);
        float wy = iy - y0f, wx = ix - x0f;
        int y0 = (int)y0f, x0 = (int)x0f;
        float vy0 = (y0 >= 0 && y0 < FM_H) ? 1.f : 0.f;
        float vy1 = (y0 >= -1 && y0 < FM_H - 1) ? 1.f : 0.f;
        float vx0 = (x0 >= 0 && x0 < FM_W) ? 1.f : 0.f;
        float vx1 = (x0 >= -1 && x0 < FM_W - 1) ? 1.f : 0.f;
        int y0c = min(max(y0, 0), FM_H - 1);
        int y1c = min(max(y0 + 1, 0), FM_H - 1);
        int x0c = min(max(x0, 0), FM_W - 1);
        int x1c = min(max(x0 + 1, 0), FM_W - 1);
        float wy0 = (1.f - wy) * vy0 * valid;
        float wy1 = wy * vy1 * valid;
        float w00 = (1.f - wx) * vx0 * wy0;
        float w10 = wx * vx1 * wy0;
        float w01 = (1.f - wx) * vx0 * wy1;
        float w11 = wx * vx1 * wy1;
        const float4* r0 = base4 + y0c * (FM_W * 16) + lane4;
        const float4* r1 = base4 + y1c * (FM_W * 16) + lane4;
        float4 v00 = __ldg(r0 + x0c * 16);
        float4 v10 = __ldg(r0 + x1c * 16);
        float4 v01 = __ldg(r1 + x0c * 16);
        float4 v11 = __ldg(r1 + x1c * 16);
        acc.x += w00 * v00.x + w10 * v10.x + w01 * v01.x + w11 * v11.x;
        acc.y += w00 * v00.y + w10 * v10.y + w01 * v01.y + w11 * v11.y;
        acc.z += w00 * v00.z + w10 * v10.z + w01 * v01.z + w11 * v11.z;
        acc.w += w00 * v00.w + w10 * v10.w + w01 * v01.w + w11 * v11.w;
    }
    return acc;
}

__global__ void __launch_bounds__(256) k_pool(const float* __restrict__ boxes) {
    __shared__ float4 s11[4][16];
    const int w = threadIdx.x >> 5;
    const int lane = threadIdx.x & 31;
    const int boxL = w >> 1;
    const int role = w & 1;
    const int half = lane >> 4;
    const int lane4 = lane & 15;
    const int box = blockIdx.x * 4 + boxL;

    const float4 b = __ldg(reinterpret_cast<const float4*>(boxes) + box);
    const float sc = 2.0f / 960.0f;
    float x1 = b.x * sc - 1.f, y1 = b.y * sc - 1.f;
    float x2 = b.z * sc - 1.f, y2 = b.w * sc - 1.f;
    float cx = 0.5f * (x1 + x2), cy = 0.5f * (y1 + y2);
    float bw = fmaxf(x2 - x1, 1e-6f), bh = fmaxf(y2 - y1, 1e-6f);
    float Ax = 0.5f * ((cx + 1.f) * (float)FM_W - 1.f);
    float Ay = 0.5f * ((cy + 1.f) * (float)FM_H - 1.f);
    float Sx = bw * (0.25f * (float)FM_W);
    float Sy = bh * (0.25f * (float)FM_H);

    const float4* base4 = reinterpret_cast<const float4*>(g_fmT);
    float4 a11;

    if (role == 0) {
        float4 a7 = accum_scale<7>(base4, Ax, Sx, Ay, Sy, 0, 49, half, lane4);
        a11 = accum_scale<11>(base4, Ax, Sx, Ay, Sy, 0, 44, half, lane4);
        a7 = half_reduce(a7);
        a11 = half_reduce(a11);
        if (lane < 16) {
            s11[boxL][lane4] = a11;
            const float s7 = (1.0f / 7.0f) * (1.0f / 7.0f);
            float4 o = make_float4(a7.x * s7, a7.y * s7, a7.z * s7, a7.w * s7);
            reinterpret_cast<float4*>(g_pooled + box * 192 + 64)[lane4] = o;
        }
    } else {
        float4 a3 = accum_scale<3>(base4, Ax, Sx, Ay, Sy, 0, 9, half, lane4);
        a11 = accum_scale<11>(base4, Ax, Sx, Ay, Sy, 44, 121, half, lane4);
        a3 = half_reduce(a3);
        a11 = half_reduce(a11);
        if (lane < 16) {
            const float s3 = (1.0f / 3.0f) * (1.0f / 3.0f);
            float4 o = make_float4(a3.x * s3, a3.y * s3, a3.z * s3, a3.w * s3);
            reinterpret_cast<float4*>(g_pooled + box * 192)[lane4] = o;
        }
    }
    __syncthreads();
    if (role == 1 && lane < 16) {
        float4 p = s11[boxL][lane4];
        const float s11c = (1.0f / 11.0f) * (1.0f / 11.0f);
        float4 o = make_float4((p.x + a11.x) * s11c, (p.y + a11.y) * s11c,
                               (p.z + a11.z) * s11c, (p.w + a11.w) * s11c);
        reinterpret_cast<float4*>(g_pooled + box * 192 + 128)[lane4] = o;
    }
}

// ---------------- kernel 4: fused MLP — register-tiled, transposed staging ----------------
// 16 boxes/block (48 shared-head rows), 256 threads, grid 256.
// Warp task tile: 8 rows x 32 cols; thread tile: 2 rows x 4 cols.
// Per k: LDS.64 (2 act rows, transposed smem) + LDG.128 (4 weight cols) -> 8 FFMA.
// bufA: X_T[64][50] (3200) then C_T[192][18] (3456)
// bufB: H_T[128][50] (6400) then h2_T[128][18] (2304)
#define STRIDE_XH 50
#define STRIDE_C  18

// One warp-task GEMM tile: rows r0,r0+1 per thread over K, weights row-major [K][NC].
template <int K>
__device__ __forceinline__ void gemm_tile(const float* __restrict__ act,  // transposed [K][stride]
                                          int stride, int r0,
                                          const float* __restrict__ wgt, int ncols, int c0,
                                          float4 bias, float4* o0, float4* o1) {
    float4 a0 = bias, a1 = bias;
#pragma unroll 4
    for (int k = 0; k < K; k++) {
        float2 x = *reinterpret_cast<const float2*>(act + k * stride + r0);
        float4 wv = __ldg(reinterpret_cast<const float4*>(wgt + k * ncols + c0));
        a0.x += x.x * wv.x; a0.y += x.x * wv.y; a0.z += x.x * wv.z; a0.w += x.x * wv.w;
        a1.x += x.y * wv.x; a1.y += x.y * wv.y; a1.z += x.y * wv.z; a1.w += x.y * wv.w;
    }
    *o0 = a0; *o1 = a1;
}

__global__ void __launch_bounds__(256) k_mlp(const float* __restrict__ w1, const float* __restrict__ b1,
                                             const float* __restrict__ w2, const float* __restrict__ b2,
                                             const float* __restrict__ p1, const float* __restrict__ p2,
                                             const float* __restrict__ pb2, float* __restrict__ out) {
    __shared__ __align__(16) float bufA[3456];
    __shared__ __align__(16) float bufB[6400];
    const int t = threadIdx.x;
    const int wg = t >> 5;
    const int lane = t & 31;
    const int cg = lane & 7;       // 8 col groups x 4 cols
    const int rg = lane >> 3;      // 4 row groups x 2 rows

    // phase 0: load pooled[16 boxes][192] -> X_T[c][row], row = box*3+s
    {
        const float4* src4 = reinterpret_cast<const float4*>(g_pooled + blockIdx.x * (16 * 192));
#pragma unroll
        for (int i = 0; i < 3; i++) {
            int v = i * 256 + t;           // v in [0,768): float4 index
            float4 val = __ldg(src4 + v);
            int idx = v * 4;               // scalar index: box*192 + s*64 + c
            int box = idx / 192;
            int rem = idx - box * 192;
            int s = rem >> 6;
            int c = rem & 63;
            int row = box * 3 + s;
            bufA[c * STRIDE_XH + row]       = val.x;
            bufA[(c + 1) * STRIDE_XH + row] = val.y;
            bufA[(c + 2) * STRIDE_XH + row] = val.z;
            bufA[(c + 3) * STRIDE_XH + row] = val.w;
        }
    }
    __syncthreads();

    // phase 1: H[48][128] = relu(X @ w1 + b1) -> H_T in bufB. 24 tasks (6 rg x 4 cg).
    for (int tt = wg; tt < 24; tt += 8) {
        int tr = tt % 6, tc = tt / 6;
        int r0 = tr * 8 + rg * 2;
        int c0 = tc * 32 + cg * 4;
        float4 bv = __ldg(reinterpret_cast<const float4*>(b1 + c0));
        float4 o0, o1;
        gemm_tile<64>(bufA, STRIDE_XH, r0, w1, 128, c0, bv, &o0, &o1);
        o0 = relu4(o0); o1 = relu4(o1);
        bufB[(c0 + 0) * STRIDE_XH + r0] = o0.x; bufB[(c0 + 0) * STRIDE_XH + r0 + 1] = o1.x;
        bufB[(c0 + 1) * STRIDE_XH + r0] = o0.y; bufB[(c0 + 1) * STRIDE_XH + r0 + 1] = o1.y;
        bufB[(c0 + 2) * STRIDE_XH + r0] = o0.z; bufB[(c0 + 2) * STRIDE_XH + r0 + 1] = o1.z;
        bufB[(c0 + 3) * STRIDE_XH + r0] = o0.w; bufB[(c0 + 3) * STRIDE_XH + r0 + 1] = o1.w;
    }
    __syncthreads();

    // phase 2: feats[48][64] = relu(H @ w2 + b2) -> C_T[s*64+c][box] in bufA. 12 tasks (6 x 2).
    for (int tt = wg; tt < 12; tt += 8) {
        int tr = tt % 6, tc = tt / 6;
        int r0 = tr * 8 + rg * 2;
        int c0 = tc * 32 + cg * 4;
        float4 bv = __ldg(reinterpret_cast<const float4*>(b2 + c0));
        float4 o0, o1;
        gemm_tile<128>(bufB, STRIDE_XH, r0, w2, 64, c0, bv, &o0, &o1);
        o0 = relu4(o0); o1 = relu4(o1);
#pragma unroll
        for (int rr = 0; rr < 2; rr++) {
            int row = r0 + rr;
            int box = row / 3;
            int s = row - box * 3;
            float4 o = rr ? o1 : o0;
            bufA[(s * 64 + c0 + 0) * STRIDE_C + box] = o.x;
            bufA[(s * 64 + c0 + 1) * STRIDE_C + box] = o.y;
            bufA[(s * 64 + c0 + 2) * STRIDE_C + box] = o.z;
            bufA[(s * 64 + c0 + 3) * STRIDE_C + box] = o.w;
        }
    }
    __syncthreads();

    // phase 3: h2[16][128] = relu(concat @ p1[0:192] + pb1eff) -> h2_T in bufB. 8 tasks (2 x 4).
    {
        int tt = wg;
        int tb = tt % 2, tc = tt / 2;
        int r0 = tb * 8 + rg * 2;      // box index
        int c0 = tc * 32 + cg * 4;
        float4 bv = *reinterpret_cast<const float4*>(g_pb1eff + c0);
        float4 o0, o1;
        gemm_tile<192>(bufA, STRIDE_C, r0, p1, 128, c0, bv, &o0, &o1);
        o0 = relu4(o0); o1 = relu4(o1);
        bufB[(c0 + 0) * STRIDE_C + r0] = o0.x; bufB[(c0 + 0) * STRIDE_C + r0 + 1] = o1.x;
        bufB[(c0 + 1) * STRIDE_C + r0] = o0.y; bufB[(c0 + 1) * STRIDE_C + r0 + 1] = o1.y;
        bufB[(c0 + 2) * STRIDE_C + r0] = o0.z; bufB[(c0 + 2) * STRIDE_C + r0 + 1] = o1.z;
        bufB[(c0 + 3) * STRIDE_C + r0] = o0.w; bufB[(c0 + 3) * STRIDE_C + r0 + 1] = o1.w;
    }
    __syncthreads();

    // phase 4: out[16][64] = relu(h2 @ p2 + pb2). 4 tasks (2 x 2), warps 0-3.
    if (wg < 4) {
        int tb = wg % 2, tc = wg / 2;
        int r0 = tb * 8 + rg * 2;      // box index
        int c0 = tc * 32 + cg * 4;
        float4 bv = __ldg(reinterpret_cast<const float4*>(pb2 + c0));
        float4 o0, o1;
        gemm_tile<128>(bufB, STRIDE_C, r0, p2, 64, c0, bv, &o0, &o1);
        o0 = relu4(o0); o1 = relu4(o1);
        *reinterpret_cast<float4*>(out + (blockIdx.x * 16 + r0) * 64 + c0) = o0;
        *reinterpret_cast<float4*>(out + (blockIdx.x * 16 + r0 + 1) * 64 + c0) = o1;
    }
}

// ---------------- launch ----------------
extern "C" void kernel_launch(void* const* d_in, const int* in_sizes, int n_in,
                              void* d_out, int out_size) {
    const float* fm    = (const float*)d_in[0];
    const float* boxes = (const float*)d_in[1];
    const float* w1    = (const float*)d_in[2];
    const float* b1    = (const float*)d_in[3];
    const float* w2    = (const float*)d_in[4];
    const float* b2    = (const float*)d_in[5];
    const float* p1    = (const float*)d_in[6];
    const float* pb1   = (const float*)d_in[7];
    const float* p2    = (const float*)d_in[8];
    const float* pb2   = (const float*)d_in[9];
    float* out = (float*)d_out;

    k_prep<<<FM_HW / 64 + 64, 256>>>(fm);
    k_headg<<<1, 128>>>(w1, b1, w2, b2, p1, pb1);
    k_pool<<<N_BOX / 4, 256>>>(boxes);
    k_mlp<<<N_BOX / 16, 256>>>(w1, b1, w2, b2, p1, p2, pb2, out);
}

// round 14
// speedup vs baseline: 1.1064x; 1.1064x over previous
#include <cuda_runtime.h>

#define FM_H 120
#define FM_W 120
#define FM_C 64
#define FM_HW (FM_H * FM_W)
#define N_BOX 4096

// ---------------- device scratch (no allocations allowed) ----------------
__device__ __align__(16) float g_fmT[FM_HW * FM_C];      // [H*W][C]
__device__ __align__(16) float g_pooled[N_BOX * 3 * 64]; // [12288 rows][64] == concat view
__device__ __align__(16) float g_feat[N_BOX * 3 * 64];   // T2: [12288][64] == [4096][192]
__device__ float g_gvec[64];
__device__ __align__(16) float g_pb1eff[128];

// ---------------- helpers ----------------
__device__ __forceinline__ float4 relu4(float4 v) {
    v.x = fmaxf(v.x, 0.f); v.y = fmaxf(v.y, 0.f);
    v.z = fmaxf(v.z, 0.f); v.w = fmaxf(v.w, 0.f);
    return v;
}

__device__ __forceinline__ float4 half_reduce(float4 a) {
    a.x += __shfl_down_sync(0xffffffffu, a.x, 16);
    a.y += __shfl_down_sync(0xffffffffu, a.y, 16);
    a.z += __shfl_down_sync(0xffffffffu, a.z, 16);
    a.w += __shfl_down_sync(0xffffffffu, a.w, 16);
    return a;
}

// ---------------- kernel 1: transpose + global mean (unchanged) ----------------
__global__ void k_prep(const float* __restrict__ fm) {
    if (blockIdx.x < FM_HW / 64) {
        __shared__ float tile[64 * 65];
        const int p0 = blockIdx.x * 64;
        const int t = threadIdx.x;
#pragma unroll
        for (int i = 0; i < 16; i++) {
            int idx = i * 256 + t;
            int c = idx >> 6, p = idx & 63;
            tile[p * 65 + c] = fm[c * FM_HW + p0 + p];
        }
        __syncthreads();
#pragma unroll
        for (int i = 0; i < 16; i++) {
            int idx = i * 256 + t;
            int p = idx >> 6, c = idx & 63;
            g_fmT[(p0 + p) * 64 + c] = tile[p * 65 + c];
        }
    } else {
        __shared__ float red[256];
        const int c = blockIdx.x - FM_HW / 64;
        float s = 0.f;
        for (int p = threadIdx.x; p < FM_HW; p += 256) s += fm[c * FM_HW + p];
        red[threadIdx.x] = s;
        __syncthreads();
        for (int st = 128; st > 0; st >>= 1) {
            if (threadIdx.x < st) red[threadIdx.x] += red[threadIdx.x + st];
            __syncthreads();
        }
        if (threadIdx.x == 0) g_gvec[c] = red[0] * (1.0f / (float)FM_HW);
    }
}

// ---------------- kernel 2: shared head on g -> pb1eff (unchanged) ----------------
__global__ void k_headg(const float* __restrict__ w1, const float* __restrict__ b1,
                        const float* __restrict__ w2, const float* __restrict__ b2,
                        const float* __restrict__ p1, const float* __restrict__ pb1) {
    __shared__ float h1[128];
    __shared__ float gh[64];
    const int t = threadIdx.x;
    {
        float acc = b1[t];
#pragma unroll 8
        for (int c = 0; c < 64; c++) acc += g_gvec[c] * w1[c * 128 + t];
        h1[t] = fmaxf(acc, 0.f);
    }
    __syncthreads();
    if (t < 64) {
        float acc = b2[t];
#pragma unroll 8
        for (int k = 0; k < 128; k++) acc += h1[k] * w2[k * 64 + t];
        gh[t] = fmaxf(acc, 0.f);
    }
    __syncthreads();
    {
        float acc = pb1[t];
#pragma unroll 8
        for (int j = 0; j < 64; j++) acc += gh[j] * p1[(192 + j) * 128 + t];
        g_pb1eff[t] = acc;
    }
}

// ---------------- kernel 3: ROI pooling (unchanged, proven) ----------------
template <int R>
__device__ __forceinline__ float4 accum_scale(const float4* __restrict__ base4,
                                              float Ax, float Sx, float Ay, float Sy,
                                              int j0, int j1, int half, int lane4) {
    const float invR = 1.0f / (float)R;
    float4 acc = make_float4(0.f, 0.f, 0.f, 0.f);
    const int steps = ((j1 - j0) + 1) >> 1;
#pragma unroll 4
    for (int i = 0; i < steps; i++) {
        int j = j0 + 2 * i + half;
        float valid = (j < j1) ? 1.f : 0.f;
        int jc = min(j, j1 - 1);
        int row = jc / R;
        int col = jc - row * R;
        float iy = Ay + Sy * ((2.0f * row + 1.0f) * invR - 1.0f);
        float ix = Ax + Sx * ((2.0f * col + 1.0f) * invR - 1.0f);
        float y0f = floorf(iy), x0f = floorf(ix);
        float wy = iy - y0f, wx = ix - x0f;
        int y0 = (int)y0f, x0 = (int)x0f;
        float vy0 = (y0 >= 0 && y0 < FM_H) ? 1.f : 0.f;
        float vy1 = (y0 >= -1 && y0 < FM_H - 1) ? 1.f : 0.f;
        float vx0 = (x0 >= 0 && x0 < FM_W) ? 1.f : 0.f;
        float vx1 = (x0 >= -1 && x0 < FM_W - 1) ? 1.f : 0.f;
        int y0c = min(max(y0, 0), FM_H - 1);
        int y1c = min(max(y0 + 1, 0), FM_H - 1);
        int x0c = min(max(x0, 0), FM_W - 1);
        int x1c = min(max(x0 + 1, 0), FM_W - 1);
        float wy0 = (1.f - wy) * vy0 * valid;
        float wy1 = wy * vy1 * valid;
        float w00 = (1.f - wx) * vx0 * wy0;
        float w10 = wx * vx1 * wy0;
        float w01 = (1.f - wx) * vx0 * wy1;
        float w11 = wx * vx1 * wy1;
        const float4* r0 = base4 + y0c * (FM_W * 16) + lane4;
        const float4* r1 = base4 + y1c * (FM_W * 16) + lane4;
        float4 v00 = __ldg(r0 + x0c * 16);
        float4 v10 = __ldg(r0 + x1c * 16);
        float4 v01 = __ldg(r1 + x0c * 16);
        float4 v11 = __ldg(r1 + x1c * 16);
        acc.x += w00 * v00.x + w10 * v10.x + w01 * v01.x + w11 * v11.x;
        acc.y += w00 * v00.y + w10 * v10.y + w01 * v01.y + w11 * v11.y;
        acc.z += w00 * v00.z + w10 * v10.z + w01 * v01.z + w11 * v11.z;
        acc.w += w00 * v00.w + w10 * v10.w + w01 * v01.w + w11 * v11.w;
    }
    return acc;
}

__global__ void __launch_bounds__(256) k_pool(const float* __restrict__ boxes) {
    __shared__ float4 s11[4][16];
    const int w = threadIdx.x >> 5;
    const int lane = threadIdx.x & 31;
    const int boxL = w >> 1;
    const int role = w & 1;
    const int half = lane >> 4;
    const int lane4 = lane & 15;
    const int box = blockIdx.x * 4 + boxL;

    const float4 b = __ldg(reinterpret_cast<const float4*>(boxes) + box);
    const float sc = 2.0f / 960.0f;
    float x1 = b.x * sc - 1.f, y1 = b.y * sc - 1.f;
    float x2 = b.z * sc - 1.f, y2 = b.w * sc - 1.f;
    float cx = 0.5f * (x1 + x2), cy = 0.5f * (y1 + y2);
    float bw = fmaxf(x2 - x1, 1e-6f), bh = fmaxf(y2 - y1, 1e-6f);
    float Ax = 0.5f * ((cx + 1.f) * (float)FM_W - 1.f);
    float Ay = 0.5f * ((cy + 1.f) * (float)FM_H - 1.f);
    float Sx = bw * (0.25f * (float)FM_W);
    float Sy = bh * (0.25f * (float)FM_H);

    const float4* base4 = reinterpret_cast<const float4*>(g_fmT);
    float4 a11;

    if (role == 0) {
        float4 a7 = accum_scale<7>(base4, Ax, Sx, Ay, Sy, 0, 49, half, lane4);
        a11 = accum_scale<11>(base4, Ax, Sx, Ay, Sy, 0, 44, half, lane4);
        a7 = half_reduce(a7);
        a11 = half_reduce(a11);
        if (lane < 16) {
            s11[boxL][lane4] = a11;
            const float s7 = (1.0f / 7.0f) * (1.0f / 7.0f);
            float4 o = make_float4(a7.x * s7, a7.y * s7, a7.z * s7, a7.w * s7);
            reinterpret_cast<float4*>(g_pooled + box * 192 + 64)[lane4] = o;
        }
    } else {
        float4 a3 = accum_scale<3>(base4, Ax, Sx, Ay, Sy, 0, 9, half, lane4);
        a11 = accum_scale<11>(base4, Ax, Sx, Ay, Sy, 44, 121, half, lane4);
        a3 = half_reduce(a3);
        a11 = half_reduce(a11);
        if (lane < 16) {
            const float s3 = (1.0f / 3.0f) * (1.0f / 3.0f);
            float4 o = make_float4(a3.x * s3, a3.y * s3, a3.z * s3, a3.w * s3);
            reinterpret_cast<float4*>(g_pooled + box * 192)[lane4] = o;
        }
    }
    __syncthreads();
    if (role == 1 && lane < 16) {
        float4 p = s11[boxL][lane4];
        const float s11c = (1.0f / 11.0f) * (1.0f / 11.0f);
        float4 o = make_float4((p.x + a11.x) * s11c, (p.y + a11.y) * s11c,
                               (p.z + a11.z) * s11c, (p.w + a11.w) * s11c);
        reinterpret_cast<float4*>(g_pooled + box * 192 + 128)[lane4] = o;
    }
}

// ---------------- kernel 4: fused GEMM1+2 (shared head on all 12288 rows) ----------------
// grid 192, 256 threads, 64 rows/block. Dynamic smem (floats):
//   phase A: sA  @0     [64 k][68]    (X transposed, 4352)
//            sW1 @4352  [64 k][128]   (8192, ends 12544)
//   phase B: sT  @0     [128 k][68]   (T1 transposed, 8704)
//            sW2 @8704  [128 k][64]   (8192, ends 16896)
#define H2_SA  0
#define H2_SW1 4352
#define H2_ST  0
#define H2_SW2 8704
#define H2_SMEM_FLOATS 16896

__global__ void __launch_bounds__(256) k_head2(const float* __restrict__ w1, const float* __restrict__ b1,
                                               const float* __restrict__ w2, const float* __restrict__ b2) {
    extern __shared__ float s[];
    const int t = threadIdx.x;
    const int blk = blockIdx.x;
    const int warp = t >> 5, lane = t & 31;

    // load X[64 rows][64] transposed -> sA[k][row]; copy w1 -> sW1
    {
        const float4* src = reinterpret_cast<const float4*>(g_pooled) + blk * 1024;
#pragma unroll
        for (int i = 0; i < 4; i++) {
            int v = i * 256 + t;
            float4 val = __ldg(src + v);
            int row = v >> 4, c4 = (v & 15) * 4;
            s[H2_SA + (c4 + 0) * 68 + row] = val.x;
            s[H2_SA + (c4 + 1) * 68 + row] = val.y;
            s[H2_SA + (c4 + 2) * 68 + row] = val.z;
            s[H2_SA + (c4 + 3) * 68 + row] = val.w;
        }
        const float4* w1f = reinterpret_cast<const float4*>(w1);
        float4* d = reinterpret_cast<float4*>(s + H2_SW1);
#pragma unroll
        for (int i = 0; i < 8; i++) d[i * 256 + t] = __ldg(w1f + i * 256 + t);
    }
    __syncthreads();

    // phase A: T1[64][128] = relu(X @ w1 + b1); thread: rows r0..r0+7, cols c0..c0+3
    float acc[8][4];
    {
        const int r0 = warp * 8, c0 = lane * 4;
        float4 bv = __ldg(reinterpret_cast<const float4*>(b1 + c0));
#pragma unroll
        for (int i = 0; i < 8; i++) { acc[i][0] = bv.x; acc[i][1] = bv.y; acc[i][2] = bv.z; acc[i][3] = bv.w; }
#pragma unroll 8
        for (int k = 0; k < 64; k++) {
            float4 a0 = *reinterpret_cast<const float4*>(s + H2_SA + k * 68 + r0);
            float4 a1 = *reinterpret_cast<const float4*>(s + H2_SA + k * 68 + r0 + 4);
            float4 w = *reinterpret_cast<const float4*>(s + H2_SW1 + k * 128 + c0);
            float av[8] = {a0.x, a0.y, a0.z, a0.w, a1.x, a1.y, a1.z, a1.w};
#pragma unroll
            for (int i = 0; i < 8; i++) {
                acc[i][0] += av[i] * w.x; acc[i][1] += av[i] * w.y;
                acc[i][2] += av[i] * w.z; acc[i][3] += av[i] * w.w;
            }
        }
    }
    __syncthreads();   // all reads of sA/sW1 done before overwrite

    // write T1 transposed -> sT[k=col][row]; load w2 -> sW2
    {
        const int r0 = warp * 8, c0 = lane * 4;
#pragma unroll
        for (int j = 0; j < 4; j++) {
            float4 v0 = make_float4(fmaxf(acc[0][j], 0.f), fmaxf(acc[1][j], 0.f),
                                    fmaxf(acc[2][j], 0.f), fmaxf(acc[3][j], 0.f));
            float4 v1 = make_float4(fmaxf(acc[4][j], 0.f), fmaxf(acc[5][j], 0.f),
                                    fmaxf(acc[6][j], 0.f), fmaxf(acc[7][j], 0.f));
            *reinterpret_cast<float4*>(s + H2_ST + (c0 + j) * 68 + r0) = v0;
            *reinterpret_cast<float4*>(s + H2_ST + (c0 + j) * 68 + r0 + 4) = v1;
        }
        const float4* w2f = reinterpret_cast<const float4*>(w2);
        float4* d = reinterpret_cast<float4*>(s + H2_SW2);
#pragma unroll
        for (int i = 0; i < 8; i++) d[i * 256 + t] = __ldg(w2f + i * 256 + t);
    }
    __syncthreads();

    // phase B: T2[64][64] = relu(T1 @ w2 + b2) -> g_feat
    {
        const int r0 = warp * 8, c0 = lane * 2;
        float2 bv = __ldg(reinterpret_cast<const float2*>(b2 + c0));
        float a2[8][2];
#pragma unroll
        for (int i = 0; i < 8; i++) { a2[i][0] = bv.x; a2[i][1] = bv.y; }
#pragma unroll 8
        for (int k = 0; k < 128; k++) {
            float4 a0 = *reinterpret_cast<const float4*>(s + H2_ST + k * 68 + r0);
            float4 a1 = *reinterpret_cast<const float4*>(s + H2_ST + k * 68 + r0 + 4);
            float2 w = *reinterpret_cast<const float2*>(s + H2_SW2 + k * 64 + c0);
            float av[8] = {a0.x, a0.y, a0.z, a0.w, a1.x, a1.y, a1.z, a1.w};
#pragma unroll
            for (int i = 0; i < 8; i++) { a2[i][0] += av[i] * w.x; a2[i][1] += av[i] * w.y; }
        }
#pragma unroll
        for (int i = 0; i < 8; i++) {
            int grow = blk * 64 + r0 + i;
            float2 o = make_float2(fmaxf(a2[i][0], 0.f), fmaxf(a2[i][1], 0.f));
            *reinterpret_cast<float2*>(g_feat + grow * 64 + c0) = o;
        }
    }
}

// ---------------- kernel 5: fused GEMM3+4 (fusion head) ----------------
// grid 128, 256 threads, 32 boxes/block. Dynamic smem (floats):
//   sA3 @0      [192 k][36]  (concat transposed, 6912)
//   sW  @6912   [64 k][128]  (p1 chunk, 8192, ends 15104)
//   sT3 @15104  [128 k][36]  (h2 transposed, 4608, ends 19712)
//   sP2 @19712  [128 k][64]  (8192, ends 27904)
#define F_SA  0
#define F_SW  6912
#define F_ST  15104
#define F_SP2 19712
#define F_SMEM_FLOATS 27904

__global__ void __launch_bounds__(256) k_fuse(const float* __restrict__ p1, const float* __restrict__ p2,
                                              const float* __restrict__ pb2, float* __restrict__ out) {
    extern __shared__ float s[];
    const int t = threadIdx.x;
    const int b0 = blockIdx.x * 32;
    const int warp = t >> 5, lane = t & 31;

    // load concat[32 boxes][192] transposed -> sA3[j][boxL]; copy p2 -> sP2
    {
        const float4* src = reinterpret_cast<const float4*>(g_feat) + b0 * 48;
#pragma unroll
        for (int i = 0; i < 6; i++) {
            int v = i * 256 + t;
            float4 val = __ldg(src + v);
            int boxL = v / 48, j4 = (v % 48) * 4;
            s[F_SA + (j4 + 0) * 36 + boxL] = val.x;
            s[F_SA + (j4 + 1) * 36 + boxL] = val.y;
            s[F_SA + (j4 + 2) * 36 + boxL] = val.z;
            s[F_SA + (j4 + 3) * 36 + boxL] = val.w;
        }
        const float4* p2f = reinterpret_cast<const float4*>(p2);
        float4* d = reinterpret_cast<float4*>(s + F_SP2);
#pragma unroll
        for (int i = 0; i < 8; i++) d[i * 256 + t] = __ldg(p2f + i * 256 + t);
    }
    __syncthreads();

    // phase A: h2[32][128] = relu(concat @ p1[0:192] + pb1eff); thread: rows r0..r0+3, cols c0..c0+3
    float acc[4][4];
    {
        const int r0 = warp * 4, c0 = lane * 4;
        float4 bv = *reinterpret_cast<const float4*>(g_pb1eff + c0);
#pragma unroll
        for (int i = 0; i < 4; i++) { acc[i][0] = bv.x; acc[i][1] = bv.y; acc[i][2] = bv.z; acc[i][3] = bv.w; }
        for (int ch = 0; ch < 3; ch++) {
            if (ch) __syncthreads();   // prior chunk compute done before overwriting sW
            {
                const float4* p1f = reinterpret_cast<const float4*>(p1) + ch * 2048;
                float4* d = reinterpret_cast<float4*>(s + F_SW);
#pragma unroll
                for (int i = 0; i < 8; i++) d[i * 256 + t] = __ldg(p1f + i * 256 + t);
            }
            __syncthreads();
#pragma unroll 8
            for (int k = 0; k < 64; k++) {
                int kg = ch * 64 + k;
                float4 a = *reinterpret_cast<const float4*>(s + F_SA + kg * 36 + r0);
                float4 w = *reinterpret_cast<const float4*>(s + F_SW + k * 128 + c0);
                acc[0][0] += a.x * w.x; acc[0][1] += a.x * w.y; acc[0][2] += a.x * w.z; acc[0][3] += a.x * w.w;
                acc[1][0] += a.y * w.x; acc[1][1] += a.y * w.y; acc[1][2] += a.y * w.z; acc[1][3] += a.y * w.w;
                acc[2][0] += a.z * w.x; acc[2][1] += a.z * w.y; acc[2][2] += a.z * w.z; acc[2][3] += a.z * w.w;
                acc[3][0] += a.w * w.x; acc[3][1] += a.w * w.y; acc[3][2] += a.w * w.z; acc[3][3] += a.w * w.w;
            }
        }
    }

    // write h2 transposed -> sT3[k=col][row] (region disjoint from sA3/sW)
    {
        const int r0 = warp * 4, c0 = lane * 4;
#pragma unroll
        for (int j = 0; j < 4; j++) {
            float4 v = make_float4(fmaxf(acc[0][j], 0.f), fmaxf(acc[1][j], 0.f),
                                   fmaxf(acc[2][j], 0.f), fmaxf(acc[3][j], 0.f));
            *reinterpret_cast<float4*>(s + F_ST + (c0 + j) * 36 + r0) = v;
        }
    }
    __syncthreads();

    // phase B: out[32][64] = relu(h2 @ p2 + pb2)
    {
        const int r0 = warp * 4, c0 = lane * 2;
        float2 bv = __ldg(reinterpret_cast<const float2*>(pb2 + c0));
        float a2[4][2];
#pragma unroll
        for (int i = 0; i < 4; i++) { a2[i][0] = bv.x; a2[i][1] = bv.y; }
#pragma unroll 8
        for (int k = 0; k < 128; k++) {
            float4 a = *reinterpret_cast<const float4*>(s + F_ST + k * 36 + r0);
            float2 w = *reinterpret_cast<const float2*>(s + F_SP2 + k * 64 + c0);
            a2[0][0] += a.x * w.x; a2[0][1] += a.x * w.y;
            a2[1][0] += a.y * w.x; a2[1][1] += a.y * w.y;
            a2[2][0] += a.z * w.x; a2[2][1] += a.z * w.y;
            a2[3][0] += a.w * w.x; a2[3][1] += a.w * w.y;
        }
#pragma unroll
        for (int i = 0; i < 4; i++) {
            float2 o = make_float2(fmaxf(a2[i][0], 0.f), fmaxf(a2[i][1], 0.f));
            *reinterpret_cast<float2*>(out + (b0 + r0 + i) * 64 + c0) = o;
        }
    }
}

// ---------------- launch ----------------
extern "C" void kernel_launch(void* const* d_in, const int* in_sizes, int n_in,
                              void* d_out, int out_size) {
    const float* fm    = (const float*)d_in[0];
    const float* boxes = (const float*)d_in[1];
    const float* w1    = (const float*)d_in[2];
    const float* b1    = (const float*)d_in[3];
    const float* w2    = (const float*)d_in[4];
    const float* b2    = (const float*)d_in[5];
    const float* p1    = (const float*)d_in[6];
    const float* pb1   = (const float*)d_in[7];
    const float* p2    = (const float*)d_in[8];
    const float* pb2   = (const float*)d_in[9];
    float* out = (float*)d_out;

    cudaFuncSetAttribute(k_head2, cudaFuncAttributeMaxDynamicSharedMemorySize,
                         H2_SMEM_FLOATS * (int)sizeof(float));
    cudaFuncSetAttribute(k_fuse, cudaFuncAttributeMaxDynamicSharedMemorySize,
                         F_SMEM_FLOATS * (int)sizeof(float));

    k_prep<<<FM_HW / 64 + 64, 256>>>(fm);
    k_headg<<<1, 128>>>(w1, b1, w2, b2, p1, pb1);
    k_pool<<<N_BOX / 4, 256>>>(boxes);
    k_head2<<<N_BOX * 3 / 64, 256, H2_SMEM_FLOATS * sizeof(float)>>>(w1, b1, w2, b2);
    k_fuse<<<N_BOX / 32, 256, F_SMEM_FLOATS * sizeof(float)>>>(p1, p2, pb2, out);
}

// round 16
// speedup vs baseline: 1.1114x; 1.0045x over previous
#include <cuda_runtime.h>

#define FM_H 120
#define FM_W 120
#define FM_C 64
#define FM_HW (FM_H * FM_W)
#define N_BOX 4096

// ---------------- device scratch ----------------
__device__ __align__(16) float g_fmT[FM_HW * FM_C];      // [H*W][C]
__device__ __align__(16) float g_pooled[N_BOX * 3 * 64]; // [12288 rows][64]
__device__ __align__(16) float g_feat[N_BOX * 3 * 64];   // T2: [12288][64] == [4096][192]
__device__ float g_gvec[64];
__device__ __align__(16) float g_pb1eff[128];

// ---------------- helpers ----------------
__device__ __forceinline__ float4 relu4(float4 v) {
    v.x = fmaxf(v.x, 0.f); v.y = fmaxf(v.y, 0.f);
    v.z = fmaxf(v.z, 0.f); v.w = fmaxf(v.w, 0.f);
    return v;
}

__device__ __forceinline__ float4 half_reduce(float4 a) {
    a.x += __shfl_down_sync(0xffffffffu, a.x, 16);
    a.y += __shfl_down_sync(0xffffffffu, a.y, 16);
    a.z += __shfl_down_sync(0xffffffffu, a.z, 16);
    a.w += __shfl_down_sync(0xffffffffu, a.w, 16);
    return a;
}

// ---------------- kernel 1: transpose + global mean (unchanged) ----------------
__global__ void k_prep(const float* __restrict__ fm) {
    if (blockIdx.x < FM_HW / 64) {
        __shared__ float tile[64 * 65];
        const int p0 = blockIdx.x * 64;
        const int t = threadIdx.x;
#pragma unroll
        for (int i = 0; i < 16; i++) {
            int idx = i * 256 + t;
            int c = idx >> 6, p = idx & 63;
            tile[p * 65 + c] = fm[c * FM_HW + p0 + p];
        }
        __syncthreads();
#pragma unroll
        for (int i = 0; i < 16; i++) {
            int idx = i * 256 + t;
            int p = idx >> 6, c = idx & 63;
            g_fmT[(p0 + p) * 64 + c] = tile[p * 65 + c];
        }
    } else {
        __shared__ float red[256];
        const int c = blockIdx.x - FM_HW / 64;
        float s = 0.f;
        for (int p = threadIdx.x; p < FM_HW; p += 256) s += fm[c * FM_HW + p];
        red[threadIdx.x] = s;
        __syncthreads();
        for (int st = 128; st > 0; st >>= 1) {
            if (threadIdx.x < st) red[threadIdx.x] += red[threadIdx.x + st];
            __syncthreads();
        }
        if (threadIdx.x == 0) g_gvec[c] = red[0] * (1.0f / (float)FM_HW);
    }
}

// ---------------- kernel 2: ROI pooling (unchanged, proven) ----------------
template <int R>
__device__ __forceinline__ float4 accum_scale(const float4* __restrict__ base4,
                                              float Ax, float Sx, float Ay, float Sy,
                                              int j0, int j1, int half, int lane4) {
    const float invR = 1.0f / (float)R;
    float4 acc = make_float4(0.f, 0.f, 0.f, 0.f);
    const int steps = ((j1 - j0) + 1) >> 1;
#pragma unroll 4
    for (int i = 0; i < steps; i++) {
        int j = j0 + 2 * i + half;
        float valid = (j < j1) ? 1.f : 0.f;
        int jc = min(j, j1 - 1);
        int row = jc / R;
        int col = jc - row * R;
        float iy = Ay + Sy * ((2.0f * row + 1.0f) * invR - 1.0f);
        float ix = Ax + Sx * ((2.0f * col + 1.0f) * invR - 1.0f);
        float y0f = floorf(iy), x0f = floorf(ix);
        float wy = iy - y0f, wx = ix - x0f;
        int y0 = (int)y0f, x0 = (int)x0f;
        float vy0 = (y0 >= 0 && y0 < FM_H) ? 1.f : 0.f;
        float vy1 = (y0 >= -1 && y0 < FM_H - 1) ? 1.f : 0.f;
        float vx0 = (x0 >= 0 && x0 < FM_W) ? 1.f : 0.f;
        float vx1 = (x0 >= -1 && x0 < FM_W - 1) ? 1.f : 0.f;
        int y0c = min(max(y0, 0), FM_H - 1);
        int y1c = min(max(y0 + 1, 0), FM_H - 1);
        int x0c = min(max(x0, 0), FM_W - 1);
        int x1c = min(max(x0 + 1, 0), FM_W - 1);
        float wy0 = (1.f - wy) * vy0 * valid;
        float wy1 = wy * vy1 * valid;
        float w00 = (1.f - wx) * vx0 * wy0;
        float w10 = wx * vx1 * wy0;
        float w01 = (1.f - wx) * vx0 * wy1;
        float w11 = wx * vx1 * wy1;
        const float4* r0 = base4 + y0c * (FM_W * 16) + lane4;
        const float4* r1 = base4 + y1c * (FM_W * 16) + lane4;
        float4 v00 = __ldg(r0 + x0c * 16);
        float4 v10 = __ldg(r0 + x1c * 16);
        float4 v01 = __ldg(r1 + x0c * 16);
        float4 v11 = __ldg(r1 + x1c * 16);
        acc.x += w00 * v00.x + w10 * v10.x + w01 * v01.x + w11 * v11.x;
        acc.y += w00 * v00.y + w10 * v10.y + w01 * v01.y + w11 * v11.y;
        acc.z += w00 * v00.z + w10 * v10.z + w01 * v01.z + w11 * v11.z;
        acc.w += w00 * v00.w + w10 * v10.w + w01 * v01.w + w11 * v11.w;
    }
    return acc;
}

__global__ void __launch_bounds__(256) k_pool(const float* __restrict__ boxes) {
    __shared__ float4 s11[4][16];
    const int w = threadIdx.x >> 5;
    const int lane = threadIdx.x & 31;
    const int boxL = w >> 1;
    const int role = w & 1;
    const int half = lane >> 4;
    const int lane4 = lane & 15;
    const int box = blockIdx.x * 4 + boxL;

    const float4 b = __ldg(reinterpret_cast<const float4*>(boxes) + box);
    const float sc = 2.0f / 960.0f;
    float x1 = b.x * sc - 1.f, y1 = b.y * sc - 1.f;
    float x2 = b.z * sc - 1.f, y2 = b.w * sc - 1.f;
    float cx = 0.5f * (x1 + x2), cy = 0.5f * (y1 + y2);
    float bw = fmaxf(x2 - x1, 1e-6f), bh = fmaxf(y2 - y1, 1e-6f);
    float Ax = 0.5f * ((cx + 1.f) * (float)FM_W - 1.f);
    float Ay = 0.5f * ((cy + 1.f) * (float)FM_H - 1.f);
    float Sx = bw * (0.25f * (float)FM_W);
    float Sy = bh * (0.25f * (float)FM_H);

    const float4* base4 = reinterpret_cast<const float4*>(g_fmT);
    float4 a11;

    if (role == 0) {
        float4 a7 = accum_scale<7>(base4, Ax, Sx, Ay, Sy, 0, 49, half, lane4);
        a11 = accum_scale<11>(base4, Ax, Sx, Ay, Sy, 0, 44, half, lane4);
        a7 = half_reduce(a7);
        a11 = half_reduce(a11);
        if (lane < 16) {
            s11[boxL][lane4] = a11;
            const float s7 = (1.0f / 7.0f) * (1.0f / 7.0f);
            float4 o = make_float4(a7.x * s7, a7.y * s7, a7.z * s7, a7.w * s7);
            reinterpret_cast<float4*>(g_pooled + box * 192 + 64)[lane4] = o;
        }
    } else {
        float4 a3 = accum_scale<3>(base4, Ax, Sx, Ay, Sy, 0, 9, half, lane4);
        a11 = accum_scale<11>(base4, Ax, Sx, Ay, Sy, 44, 121, half, lane4);
        a3 = half_reduce(a3);
        a11 = half_reduce(a11);
        if (lane < 16) {
            const float s3 = (1.0f / 3.0f) * (1.0f / 3.0f);
            float4 o = make_float4(a3.x * s3, a3.y * s3, a3.z * s3, a3.w * s3);
            reinterpret_cast<float4*>(g_pooled + box * 192)[lane4] = o;
        }
    }
    __syncthreads();
    if (role == 1 && lane < 16) {
        float4 p = s11[boxL][lane4];
        const float s11c = (1.0f / 11.0f) * (1.0f / 11.0f);
        float4 o = make_float4((p.x + a11.x) * s11c, (p.y + a11.y) * s11c,
                               (p.z + a11.z) * s11c, (p.w + a11.w) * s11c);
        reinterpret_cast<float4*>(g_pooled + box * 192 + 128)[lane4] = o;
    }
}

// ---------------- kernel 3: fused GEMM1+2, 32 rows/block, grid 384 ----------------
// smem (floats): sA @0 [64][36]=2304; sW1 @2304 [64][128]=8192 (end 10496)
//                sT @0 [128][36]=4608; sW2 @4608 [128][64]=8192 (end 12800)
// Block 0 additionally computes g_pb1eff (replaces k_headg).
#define H2_SA  0
#define H2_SW1 2304
#define H2_ST  0
#define H2_SW2 4608
#define H2_SMEM_FLOATS 12800

__global__ void __launch_bounds__(256) k_head2(const float* __restrict__ w1, const float* __restrict__ b1,
                                               const float* __restrict__ w2, const float* __restrict__ b2,
                                               const float* __restrict__ p1, const float* __restrict__ pb1) {
    extern __shared__ float s[];
    const int t = threadIdx.x;
    const int blk = blockIdx.x;
    const int warp = t >> 5, lane = t & 31;

    // load X[32 rows][64] transposed -> sA[k][row]; copy w1 -> sW1
    {
        const float4* src = reinterpret_cast<const float4*>(g_pooled) + blk * 512;
#pragma unroll
        for (int i = 0; i < 2; i++) {
            int v = i * 256 + t;
            float4 val = __ldg(src + v);
            int row = v >> 4, c4 = (v & 15) * 4;
            s[H2_SA + (c4 + 0) * 36 + row] = val.x;
            s[H2_SA + (c4 + 1) * 36 + row] = val.y;
            s[H2_SA + (c4 + 2) * 36 + row] = val.z;
            s[H2_SA + (c4 + 3) * 36 + row] = val.w;
        }
        const float4* w1f = reinterpret_cast<const float4*>(w1);
        float4* d = reinterpret_cast<float4*>(s + H2_SW1);
#pragma unroll
        for (int i = 0; i < 8; i++) d[i * 256 + t] = __ldg(w1f + i * 256 + t);
    }
    __syncthreads();

    // phase A: T1[32][128] = relu(X @ w1 + b1); thread: rows 4w..4w+3, cols 4lane..4lane+3
    float acc[4][4];
    {
        const int r0 = warp * 4, c0 = lane * 4;
        float4 bv = __ldg(reinterpret_cast<const float4*>(b1 + c0));
#pragma unroll
        for (int i = 0; i < 4; i++) { acc[i][0] = bv.x; acc[i][1] = bv.y; acc[i][2] = bv.z; acc[i][3] = bv.w; }
#pragma unroll 8
        for (int k = 0; k < 64; k++) {
            float4 a = *reinterpret_cast<const float4*>(s + H2_SA + k * 36 + r0);
            float4 w = *reinterpret_cast<const float4*>(s + H2_SW1 + k * 128 + c0);
            acc[0][0] += a.x * w.x; acc[0][1] += a.x * w.y; acc[0][2] += a.x * w.z; acc[0][3] += a.x * w.w;
            acc[1][0] += a.y * w.x; acc[1][1] += a.y * w.y; acc[1][2] += a.y * w.z; acc[1][3] += a.y * w.w;
            acc[2][0] += a.z * w.x; acc[2][1] += a.z * w.y; acc[2][2] += a.z * w.z; acc[2][3] += a.z * w.w;
            acc[3][0] += a.w * w.x; acc[3][1] += a.w * w.y; acc[3][2] += a.w * w.z; acc[3][3] += a.w * w.w;
        }
    }
    __syncthreads();   // sA/sW1 reads complete before overwrite

    // write T1 transposed -> sT[col][row]; load w2 -> sW2
    {
        const int r0 = warp * 4, c0 = lane * 4;
#pragma unroll
        for (int j = 0; j < 4; j++) {
            float4 v = make_float4(fmaxf(acc[0][j], 0.f), fmaxf(acc[1][j], 0.f),
                                   fmaxf(acc[2][j], 0.f), fmaxf(acc[3][j], 0.f));
            *reinterpret_cast<float4*>(s + H2_ST + (c0 + j) * 36 + r0) = v;
        }
        const float4* w2f = reinterpret_cast<const float4*>(w2);
        float4* d = reinterpret_cast<float4*>(s + H2_SW2);
#pragma unroll
        for (int i = 0; i < 8; i++) d[i * 256 + t] = __ldg(w2f + i * 256 + t);
    }
    __syncthreads();

    // phase B: T2[32][64] = relu(T1 @ w2 + b2) -> g_feat
    {
        const int r0 = warp * 4, c0 = lane * 2;
        float2 bv = __ldg(reinterpret_cast<const float2*>(b2 + c0));
        float a2[4][2];
#pragma unroll
        for (int i = 0; i < 4; i++) { a2[i][0] = bv.x; a2[i][1] = bv.y; }
#pragma unroll 8
        for (int k = 0; k < 128; k++) {
            float4 a = *reinterpret_cast<const float4*>(s + H2_ST + k * 36 + r0);
            float2 w = *reinterpret_cast<const float2*>(s + H2_SW2 + k * 64 + c0);
            a2[0][0] += a.x * w.x; a2[0][1] += a.x * w.y;
            a2[1][0] += a.y * w.x; a2[1][1] += a.y * w.y;
            a2[2][0] += a.z * w.x; a2[2][1] += a.z * w.y;
            a2[3][0] += a.w * w.x; a2[3][1] += a.w * w.y;
        }
#pragma unroll
        for (int i = 0; i < 4; i++) {
            int grow = blk * 32 + r0 + i;
            float2 o = make_float2(fmaxf(a2[i][0], 0.f), fmaxf(a2[i][1], 0.f));
            *reinterpret_cast<float2*>(g_feat + grow * 64 + c0) = o;
        }
    }

    // block 0: compute pb1eff = pb1 + relu-head(gvec) @ p1[192:256]  (replaces k_headg)
    if (blk == 0) {
        __syncthreads();           // smem free for reuse
        if (t < 128) {
            float acc1 = __ldg(b1 + t);
#pragma unroll 8
            for (int c = 0; c < 64; c++) acc1 += g_gvec[c] * __ldg(w1 + c * 128 + t);
            s[t] = fmaxf(acc1, 0.f);           // h1
        }
        __syncthreads();
        if (t < 64) {
            float acc2 = __ldg(b2 + t);
#pragma unroll 8
            for (int k = 0; k < 128; k++) acc2 += s[k] * __ldg(w2 + k * 64 + t);
            s[128 + t] = fmaxf(acc2, 0.f);     // gh
        }
        __syncthreads();
        if (t < 128) {
            float acc3 = __ldg(pb1 + t);
#pragma unroll 8
            for (int j = 0; j < 64; j++) acc3 += s[128 + j] * __ldg(p1 + (192 + j) * 128 + t);
            g_pb1eff[t] = acc3;
        }
    }
}

// ---------------- kernel 4: fused GEMM3+4, 16 boxes/block, grid 256 ----------------
// smem (floats): sA3 @0 [192][20]=3840; sW @3840 [64][128]=8192 (end 12032)
//                sT3 @0 [128][20]=2560; sP2 @2560 [128][64]=8192 (end 10752)
#define F_SA  0
#define F_SW  3840
#define F_ST  0
#define F_SP2 2560
#define F_SMEM_FLOATS 12032

__global__ void __launch_bounds__(256) k_fuse(const float* __restrict__ p1, const float* __restrict__ p2,
                                              const float* __restrict__ pb2, float* __restrict__ out) {
    extern __shared__ float s[];
    const int t = threadIdx.x;
    const int b0 = blockIdx.x * 16;
    const int warp = t >> 5, lane = t & 31;

    // load concat[16 boxes][192] transposed -> sA3[j][boxL]
    {
        const float4* src = reinterpret_cast<const float4*>(g_feat) + b0 * 48;
#pragma unroll
        for (int i = 0; i < 3; i++) {
            int v = i * 256 + t;
            float4 val = __ldg(src + v);
            int boxL = v / 48, j4 = (v % 48) * 4;
            s[F_SA + (j4 + 0) * 20 + boxL] = val.x;
            s[F_SA + (j4 + 1) * 20 + boxL] = val.y;
            s[F_SA + (j4 + 2) * 20 + boxL] = val.z;
            s[F_SA + (j4 + 3) * 20 + boxL] = val.w;
        }
    }

    // phase A: h2[16][128] = relu(concat @ p1[0:192] + pb1eff)
    // thread: boxes 2w, 2w+1; cols 4lane..4lane+3.  p1 staged in 3 chunks.
    float acc[2][4];
    {
        const int r0 = warp * 2, c0 = lane * 4;
        float4 bv = *reinterpret_cast<const float4*>(g_pb1eff + c0);
        acc[0][0] = bv.x; acc[0][1] = bv.y; acc[0][2] = bv.z; acc[0][3] = bv.w;
        acc[1][0] = bv.x; acc[1][1] = bv.y; acc[1][2] = bv.z; acc[1][3] = bv.w;
        for (int ch = 0; ch < 3; ch++) {
            __syncthreads();   // protects sA3 load (ch=0) and prior-chunk sW reads
            {
                const float4* p1f = reinterpret_cast<const float4*>(p1) + ch * 2048;
                float4* d = reinterpret_cast<float4*>(s + F_SW);
#pragma unroll
                for (int i = 0; i < 8; i++) d[i * 256 + t] = __ldg(p1f + i * 256 + t);
            }
            __syncthreads();
#pragma unroll 8
            for (int k = 0; k < 64; k++) {
                int kg = ch * 64 + k;
                float2 a = *reinterpret_cast<const float2*>(s + F_SA + kg * 20 + r0);
                float4 w = *reinterpret_cast<const float4*>(s + F_SW + k * 128 + c0);
                acc[0][0] += a.x * w.x; acc[0][1] += a.x * w.y; acc[0][2] += a.x * w.z; acc[0][3] += a.x * w.w;
                acc[1][0] += a.y * w.x; acc[1][1] += a.y * w.y; acc[1][2] += a.y * w.z; acc[1][3] += a.y * w.w;
            }
        }
    }
    __syncthreads();   // all sA3/sW reads done before overwrite

    // write h2 transposed -> sT3[col][box]; load p2 -> sP2
    {
        const int r0 = warp * 2, c0 = lane * 4;
#pragma unroll
        for (int j = 0; j < 4; j++) {
            float2 v = make_float2(fmaxf(acc[0][j], 0.f), fmaxf(acc[1][j], 0.f));
            *reinterpret_cast<float2*>(s + F_ST + (c0 + j) * 20 + r0) = v;
        }
        const float4* p2f = reinterpret_cast<const float4*>(p2);
        float4* d = reinterpret_cast<float4*>(s + F_SP2);
#pragma unroll
        for (int i = 0; i < 8; i++) d[i * 256 + t] = __ldg(p2f + i * 256 + t);
    }
    __syncthreads();

    // phase B: out[16][64] = relu(h2 @ p2 + pb2); boxes 2w,2w+1; cols 2lane..2lane+1
    {
        const int r0 = warp * 2, c0 = lane * 2;
        float2 bv = __ldg(reinterpret_cast<const float2*>(pb2 + c0));
        float a2[2][2] = {{bv.x, bv.y}, {bv.x, bv.y}};
#pragma unroll 8
        for (int k = 0; k < 128; k++) {
            float2 a = *reinterpret_cast<const float2*>(s + F_ST + k * 20 + r0);
            float2 w = *reinterpret_cast<const float2*>(s + F_SP2 + k * 64 + c0);
            a2[0][0] += a.x * w.x; a2[0][1] += a.x * w.y;
            a2[1][0] += a.y * w.x; a2[1][1] += a.y * w.y;
        }
#pragma unroll
        for (int i = 0; i < 2; i++) {
            float2 o = make_float2(fmaxf(a2[i][0], 0.f), fmaxf(a2[i][1], 0.f));
            *reinterpret_cast<float2*>(out + (b0 + r0 + i) * 64 + c0) = o;
        }
    }
}

// ---------------- launch ----------------
extern "C" void kernel_launch(void* const* d_in, const int* in_sizes, int n_in,
                              void* d_out, int out_size) {
    const float* fm    = (const float*)d_in[0];
    const float* boxes = (const float*)d_in[1];
    const float* w1    = (const float*)d_in[2];
    const float* b1    = (const float*)d_in[3];
    const float* w2    = (const float*)d_in[4];
    const float* b2    = (const float*)d_in[5];
    const float* p1    = (const float*)d_in[6];
    const float* pb1   = (const float*)d_in[7];
    const float* p2    = (const float*)d_in[8];
    const float* pb2   = (const float*)d_in[9];
    float* out = (float*)d_out;

    cudaFuncSetAttribute(k_head2, cudaFuncAttributeMaxDynamicSharedMemorySize,
                         H2_SMEM_FLOATS * (int)sizeof(float));
    cudaFuncSetAttribute(k_fuse, cudaFuncAttributeMaxDynamicSharedMemorySize,
                         F_SMEM_FLOATS * (int)sizeof(float));

    k_prep<<<FM_HW / 64 + 64, 256>>>(fm);
    k_pool<<<N_BOX / 4, 256>>>(boxes);
    k_head2<<<N_BOX * 3 / 32, 256, H2_SMEM_FLOATS * sizeof(float)>>>(w1, b1, w2, b2, p1, pb1);
    k_fuse<<<N_BOX / 16, 256, F_SMEM_FLOATS * sizeof(float)>>>(p1, p2, pb2, out);
}